// round 2
// baseline (speedup 1.0000x reference)
#include <cuda_runtime.h>
#include <math.h>
#include <stdint.h>

// LiquidNNSensorModel: 2-layer CfC RNN, B=256, T=1024, S=8, H=256.
// R2: weight-stationary 8-CTA-cluster kernel. 16 clusters x 8 CTAs = 128 CTAs,
// each CTA owns 32 output neurons; recurrent weight slices live in SMEM for all
// 1024 steps; h-state replicated per CTA, exchanged via st.shared::cluster +
// 2 cluster barriers per step. 128 threads/CTA = 32 o x 4 batch-groups,
// 4 batches per thread (cluster handles 16 batches).

#define NB 256
#define NT 1024
#define NS 8
#define NH 256
#define CS 8            // cluster size
#define GC 16           // batches per cluster
#define NCTA 128
#define NTHR 128

// ---- global scratch (no allocation allowed) ----
// per-rank weight slices, deinterleaved k-quad layout: [rank][kb=64][ol=32] float4
__device__ float4 g_Ag[CS * 64 * 32];   // cell0 gate-h   gh_w0
__device__ float4 g_Ab[CS * 64 * 32];   // cell0 bb-h     bb_w0[:, 8:264]
__device__ float4 g_Hg[CS * 64 * 32];   // cell1 gate-h   gh_w1
__device__ float4 g_Hb[CS * 64 * 32];   // cell1 bb-h     bb_w1[:, 256:512]
// cell1 x-part streamed each step, interleaved pairs: [rank][kb][ol][2 float4]
__device__ float4 g_BX[CS * 64 * 32 * 2];
__device__ float2 g_WX0[NS * NH];       // cell0 x-part (gx_w0, bb_w0[:, :8]) by [k][o]
__device__ float  g_bias[6 * NH];       // bg0, bf0, sp0, bg1, bf1, sp1
__device__ float  g_dtT[NT * NB];       // transposed dt: [t][b]

// ---------------------------------------------------------------------------
__global__ void prep_dt_kernel(const float* __restrict__ ts) {
    int i = blockIdx.x * blockDim.x + threadIdx.x;
    if (i >= NB * NT) return;
    int b = i / NT, t = i - b * NT;
    float dt = 1.0f;
    if (t > 0) dt = ts[i] - ts[i - 1];
    g_dtT[t * NB + b] = fmaxf(dt, 1e-6f);
}

__global__ void prep_w_kernel(
    const float* __restrict__ bb_w0, const float* __restrict__ bb_b0,
    const float* __restrict__ gx_w0, const float* __restrict__ gx_b0,
    const float* __restrict__ gh_w0, const float* __restrict__ gb0,
    const float* __restrict__ lt0,
    const float* __restrict__ bb_w1, const float* __restrict__ bb_b1,
    const float* __restrict__ gx_w1, const float* __restrict__ gx_b1,
    const float* __restrict__ gh_w1, const float* __restrict__ gb1,
    const float* __restrict__ lt1)
{
    const int kb = blockIdx.x;    // 0..63
    const int o  = threadIdx.x;   // 0..255
    const int k0 = kb * 4;
    const int rank = o >> 5, ol = o & 31;
    const int base = (rank * 64 + kb) * 32 + ol;

    { const float* p = gh_w0 + o * NH;
      g_Ag[base] = make_float4(p[k0], p[k0+1], p[k0+2], p[k0+3]); }
    { const float* p = bb_w0 + o * (NS + NH) + NS;
      g_Ab[base] = make_float4(p[k0], p[k0+1], p[k0+2], p[k0+3]); }
    { const float* p = gh_w1 + o * NH;
      g_Hg[base] = make_float4(p[k0], p[k0+1], p[k0+2], p[k0+3]); }
    { const float* p = bb_w1 + o * (2 * NH) + NH;
      g_Hb[base] = make_float4(p[k0], p[k0+1], p[k0+2], p[k0+3]); }
    { const float* g = gx_w1 + o * NH;
      const float* b = bb_w1 + o * (2 * NH);
      g_BX[base * 2 + 0] = make_float4(g[k0],   b[k0],   g[k0+1], b[k0+1]);
      g_BX[base * 2 + 1] = make_float4(g[k0+2], b[k0+2], g[k0+3], b[k0+3]); }
    if (kb == 0) {
        for (int k = 0; k < NS; k++)
            g_WX0[k * NH + o] = make_float2(gx_w0[o * NS + k], bb_w0[o * (NS + NH) + k]);
        g_bias[0 * NH + o] = gx_b0[o] + gb0[o];
        g_bias[1 * NH + o] = bb_b0[o];
        g_bias[2 * NH + o] = log1pf(expf(lt0[o]));
        g_bias[3 * NH + o] = gx_b1[o] + gb1[o];
        g_bias[4 * NH + o] = bb_b1[o];
        g_bias[5 * NH + o] = log1pf(expf(lt1[o]));
    }
}

// ---------------------------------------------------------------------------
__device__ __forceinline__ float fast_tanh(float x) {
    float y; asm("tanh.approx.f32 %0, %1;" : "=f"(y) : "f"(x)); return y;
}
__device__ __forceinline__ float cfc_one(float ag, float af, float sp, float dt, float hold) {
    const float g = 1.f / (1.f + __expf(-ag));
    const float f = fast_tanh(af);
    const float d = __expf(-dt * (sp + fabsf(g)));
    return d * hold + (1.f - d) * f;
}
__device__ __forceinline__ void st_cluster_f4(uint32_t saddr, uint32_t rank, float4 v) {
    uint32_t ra;
    asm volatile("mapa.shared::cluster.u32 %0, %1, %2;" : "=r"(ra) : "r"(saddr), "r"(rank));
    asm volatile("st.shared::cluster.v4.f32 [%0], {%1,%2,%3,%4};"
                 :: "r"(ra), "f"(v.x), "f"(v.y), "f"(v.z), "f"(v.w) : "memory");
}
#define CLUSTER_SYNC() do { \
    asm volatile("barrier.cluster.arrive.aligned;" ::: "memory"); \
    asm volatile("barrier.cluster.wait.aligned;"   ::: "memory"); \
} while (0)

#define ACC4(WG, WB, HV) \
    ag0 = fmaf((WG), (HV).x, ag0); af0 = fmaf((WB), (HV).x, af0); \
    ag1 = fmaf((WG), (HV).y, ag1); af1 = fmaf((WB), (HV).y, af1); \
    ag2 = fmaf((WG), (HV).z, ag2); af2 = fmaf((WB), (HV).z, af2); \
    ag3 = fmaf((WG), (HV).w, ag3); af3 = fmaf((WB), (HV).w, af3);

// SMEM byte layout
#define OFF_AG 0
#define OFF_AB 32768
#define OFF_HG 65536
#define OFF_HB 98304
#define OFF_H0 131072           // [2][256][16] floats = 32768 B
#define OFF_H1 163840           // 32768 B
#define OFF_XN 196608           // [8][16] floats = 512 B
#define OFF_DT 197120           // 16 floats
#define OFF_LAT 197184          // 64 floats
#define SMEM_BYTES 197440

__global__ void __launch_bounds__(NTHR, 1) __cluster_dims__(CS, 1, 1)
liquid_cluster_kernel(
    const float* __restrict__ xs,       // [B,T,S]
    const float* __restrict__ ln_g, const float* __restrict__ ln_b,
    const float* __restrict__ lp_w, const float* __restrict__ lp_b,
    const float* __restrict__ r1_w, const float* __restrict__ r1_b,
    const float* __restrict__ r2_w, const float* __restrict__ r2_b,
    float* __restrict__ out)
{
    extern __shared__ char smem[];
    float4* Ag = (float4*)(smem + OFF_AG);
    float4* Ab = (float4*)(smem + OFF_AB);
    float4* Hg = (float4*)(smem + OFF_HG);
    float4* Hb = (float4*)(smem + OFF_HB);
    float*  h0 = (float*)(smem + OFF_H0);    // [buf][k][b]
    float*  h1 = (float*)(smem + OFF_H1);
    float*  xn = (float*)(smem + OFF_XN);    // [k][b]
    float*  dts = (float*)(smem + OFF_DT);
    float*  lat = (float*)(smem + OFF_LAT);

    const uint32_t sm_base = (uint32_t)__cvta_generic_to_shared(smem);
    const uint32_t h0_u = sm_base + OFF_H0;
    const uint32_t h1_u = sm_base + OFF_H1;

    const int tid  = threadIdx.x;
    const int lane = tid & 31;
    const int bg   = tid >> 5;          // warp id = batch group
    const int bb   = bg * 4;            // first local batch of this thread
    const int rank = blockIdx.x & 7;
    const int cid  = blockIdx.x >> 3;
    const int b0   = cid * GC;          // first global batch of cluster
    const int o_glob = rank * 32 + lane;

    // ---- load resident weight slices (coalesced) ----
    for (int i = tid; i < 2048; i += NTHR) {
        Ag[i] = g_Ag[rank * 2048 + i];
        Ab[i] = g_Ab[rank * 2048 + i];
        Hg[i] = g_Hg[rank * 2048 + i];
        Hb[i] = g_Hb[rank * 2048 + i];
    }
    // zero both h buffers
    for (int i = tid; i < 8192; i += NTHR) { h0[i] = 0.f; h1[i] = 0.f; }

    // per-thread constants
    const float rbg0 = g_bias[0 * NH + o_glob];
    const float rbf0 = g_bias[1 * NH + o_glob];
    const float rsp0 = g_bias[2 * NH + o_glob];
    const float rbg1 = g_bias[3 * NH + o_glob];
    const float rbf1 = g_bias[4 * NH + o_glob];
    const float rsp1 = g_bias[5 * NH + o_glob];
    float2 wx[NS];
    #pragma unroll
    for (int k = 0; k < NS; k++) wx[k] = g_WX0[k * NH + o_glob];

    // LN params + prefetch registers (threads 0..15 = one per cluster batch)
    float lng[NS], lnb[NS];
    float4 px0, px1; float pdt = 1.f;
    if (tid < GC) {
        #pragma unroll
        for (int k = 0; k < NS; k++) { lng[k] = ln_g[k]; lnb[k] = ln_b[k]; }
        const int gb = b0 + tid;
        const float4* xp = (const float4*)(xs + (size_t)gb * NT * NS);
        px0 = xp[0]; px1 = xp[1];
        pdt = g_dtT[0 * NB + gb];
    }
    __syncthreads();
    CLUSTER_SYNC();

    const float4* BXp = g_BX + rank * 4096;
    int cur = 0;

    for (int t = 0; t < NT; t++) {
        const int nxt = cur ^ 1;

        // ---- publish layernormed x + dt for this step ----
        if (tid < GC) {
            float x[NS] = {px0.x, px0.y, px0.z, px0.w, px1.x, px1.y, px1.z, px1.w};
            float mu = 0.f;
            #pragma unroll
            for (int k = 0; k < NS; k++) mu += x[k];
            mu *= 0.125f;
            float var = 0.f;
            #pragma unroll
            for (int k = 0; k < NS; k++) { float d = x[k] - mu; var += d * d; }
            var *= 0.125f;
            const float inv = rsqrtf(var + 1e-5f);
            #pragma unroll
            for (int k = 0; k < NS; k++)
                xn[k * GC + tid] = (x[k] - mu) * inv * lng[k] + lnb[k];
            dts[tid] = pdt;
        }
        __syncthreads();
        // prefetch next step
        if (tid < GC) {
            const int tt = (t + 1 < NT) ? t + 1 : NT - 1;
            const int gb = b0 + tid;
            const float4* xp = (const float4*)(xs + ((size_t)gb * NT + tt) * NS);
            px0 = xp[0]; px1 = xp[1];
            pdt = g_dtT[tt * NB + gb];
        }

        // =================== stage A: CfC cell 0 ===================
        float ag0 = rbg0, ag1 = rbg0, ag2 = rbg0, ag3 = rbg0;
        float af0 = rbf0, af1 = rbf0, af2 = rbf0, af3 = rbf0;
        #pragma unroll
        for (int k = 0; k < NS; k++) {
            const float4 xv = *(const float4*)(xn + k * GC + bb);
            ACC4(wx[k].x, wx[k].y, xv);
        }
        {
            const float* hc = h0 + cur * 4096;
            #pragma unroll 4
            for (int kb = 0; kb < 64; kb++) {
                const float4 wg = Ag[kb * 32 + lane];
                const float4 wb = Ab[kb * 32 + lane];
                const float4 v0 = *(const float4*)(hc + (kb * 4 + 0) * GC + bb);
                const float4 v1 = *(const float4*)(hc + (kb * 4 + 1) * GC + bb);
                const float4 v2 = *(const float4*)(hc + (kb * 4 + 2) * GC + bb);
                const float4 v3 = *(const float4*)(hc + (kb * 4 + 3) * GC + bb);
                ACC4(wg.x, wb.x, v0);
                ACC4(wg.y, wb.y, v1);
                ACC4(wg.z, wb.z, v2);
                ACC4(wg.w, wb.w, v3);
            }
            const float4 hold = *(const float4*)(hc + o_glob * GC + bb);
            float4 hn;
            hn.x = cfc_one(ag0, af0, rsp0, dts[bb + 0], hold.x);
            hn.y = cfc_one(ag1, af1, rsp0, dts[bb + 1], hold.y);
            hn.z = cfc_one(ag2, af2, rsp0, dts[bb + 2], hold.z);
            hn.w = cfc_one(ag3, af3, rsp0, dts[bb + 3], hold.w);
            const uint32_t a = h0_u + (uint32_t)((nxt * 4096 + o_glob * GC + bb) * 4);
            #pragma unroll
            for (int r = 0; r < CS; r++) st_cluster_f4(a, (uint32_t)r, hn);
        }
        CLUSTER_SYNC();

        // =================== stage B: CfC cell 1 ===================
        ag0 = rbg1; ag1 = rbg1; ag2 = rbg1; ag3 = rbg1;
        af0 = rbf1; af1 = rbf1; af2 = rbf1; af3 = rbf1;
        {
            const float* hx = h0 + nxt * 4096;   // cell1 input = new h0
            const float* hc = h1 + cur * 4096;   // cell1 state
            #pragma unroll 2
            for (int kb = 0; kb < 64; kb++) {
                const float4 p0 = BXp[(kb * 32 + lane) * 2 + 0];
                const float4 p1 = BXp[(kb * 32 + lane) * 2 + 1];
                const float4 x0 = *(const float4*)(hx + (kb * 4 + 0) * GC + bb);
                const float4 x1 = *(const float4*)(hx + (kb * 4 + 1) * GC + bb);
                const float4 x2 = *(const float4*)(hx + (kb * 4 + 2) * GC + bb);
                const float4 x3 = *(const float4*)(hx + (kb * 4 + 3) * GC + bb);
                ACC4(p0.x, p0.y, x0);
                ACC4(p0.z, p0.w, x1);
                ACC4(p1.x, p1.y, x2);
                ACC4(p1.z, p1.w, x3);
                const float4 wg = Hg[kb * 32 + lane];
                const float4 wb = Hb[kb * 32 + lane];
                const float4 u0 = *(const float4*)(hc + (kb * 4 + 0) * GC + bb);
                const float4 u1 = *(const float4*)(hc + (kb * 4 + 1) * GC + bb);
                const float4 u2 = *(const float4*)(hc + (kb * 4 + 2) * GC + bb);
                const float4 u3 = *(const float4*)(hc + (kb * 4 + 3) * GC + bb);
                ACC4(wg.x, wb.x, u0);
                ACC4(wg.y, wb.y, u1);
                ACC4(wg.z, wb.z, u2);
                ACC4(wg.w, wb.w, u3);
            }
            const float4 hold = *(const float4*)(hc + o_glob * GC + bb);
            float4 hn;
            hn.x = cfc_one(ag0, af0, rsp1, dts[bb + 0], hold.x);
            hn.y = cfc_one(ag1, af1, rsp1, dts[bb + 1], hold.y);
            hn.z = cfc_one(ag2, af2, rsp1, dts[bb + 2], hold.z);
            hn.w = cfc_one(ag3, af3, rsp1, dts[bb + 3], hold.w);
            const uint32_t a = h1_u + (uint32_t)((nxt * 4096 + o_glob * GC + bb) * 4);
            #pragma unroll
            for (int r = 0; r < CS; r++) st_cluster_f4(a, (uint32_t)r, hn);
        }
        CLUSTER_SYNC();
        cur = nxt;
    }

    // =================== head: latent + risk (2 batches per CTA) ===================
    const float* hf = h1 + cur * 4096;   // [k][b]
    if (tid < 64) {
        const int i = tid >> 5;              // 0/1
        const int l = tid & 31;
        const int lb = rank * 2 + i;
        const int gb = b0 + lb;
        const float* wrow = lp_w + l * NH;
        float acc = lp_b[l];
        for (int k = 0; k < NH; k++) acc = fmaf(hf[k * GC + lb], __ldg(wrow + k), acc);
        const float latv = tanhf(acc);
        lat[i * 32 + l] = latv;
        out[(size_t)gb * 32 + l] = latv;
    }
    __syncthreads();
    if (tid < 64) {
        const int i = tid >> 5;
        const int j = tid & 31;
        const int gb = b0 + rank * 2 + i;
        const float* wrow = r1_w + j * 32;
        float acc = r1_b[j];
        #pragma unroll
        for (int k = 0; k < 32; k++) acc = fmaf(lat[i * 32 + k], __ldg(wrow + k), acc);
        const float hid = 0.5f * acc * (1.f + erff(acc * 0.70710678118654752f));
        float v = hid * __ldg(r2_w + j);
        #pragma unroll
        for (int off = 16; off; off >>= 1) v += __shfl_xor_sync(0xffffffffu, v, off);
        if (j == 0) {
            const float risk = 1.f / (1.f + __expf(-(v + r2_b[0])));
            out[NB * 32 + gb] = risk;
        }
    }
}

// ---------------------------------------------------------------------------
extern "C" void kernel_launch(void* const* d_in, const int* in_sizes, int n_in,
                              void* d_out, int out_size) {
    const float* xs    = (const float*)d_in[0];
    const float* ts    = (const float*)d_in[1];
    const float* ln_g  = (const float*)d_in[2];
    const float* ln_b  = (const float*)d_in[3];
    const float* bb_w0 = (const float*)d_in[4];
    const float* bb_b0 = (const float*)d_in[5];
    const float* gx_w0 = (const float*)d_in[6];
    const float* gx_b0 = (const float*)d_in[7];
    const float* gh_w0 = (const float*)d_in[8];
    const float* gb0   = (const float*)d_in[9];
    const float* lt0   = (const float*)d_in[10];
    const float* bb_w1 = (const float*)d_in[11];
    const float* bb_b1 = (const float*)d_in[12];
    const float* gx_w1 = (const float*)d_in[13];
    const float* gx_b1 = (const float*)d_in[14];
    const float* gh_w1 = (const float*)d_in[15];
    const float* gb1   = (const float*)d_in[16];
    const float* lt1   = (const float*)d_in[17];
    const float* lp_w  = (const float*)d_in[18];
    const float* lp_b  = (const float*)d_in[19];
    const float* r1_w  = (const float*)d_in[20];
    const float* r1_b  = (const float*)d_in[21];
    const float* r2_w  = (const float*)d_in[22];
    const float* r2_b  = (const float*)d_in[23];
    float* out = (float*)d_out;

    static int configured = 0;
    if (!configured) {
        cudaFuncSetAttribute(liquid_cluster_kernel,
                             cudaFuncAttributeMaxDynamicSharedMemorySize, SMEM_BYTES);
        configured = 1;
    }

    prep_dt_kernel<<<(NB * NT) / 256, 256>>>(ts);
    prep_w_kernel<<<64, 256>>>(bb_w0, bb_b0, gx_w0, gx_b0, gh_w0, gb0, lt0,
                               bb_w1, bb_b1, gx_w1, gx_b1, gh_w1, gb1, lt1);
    liquid_cluster_kernel<<<NCTA, NTHR, SMEM_BYTES>>>(
        xs, ln_g, ln_b, lp_w, lp_b, r1_w, r1_b, r2_w, r2_b, out);
}

// round 3
// speedup vs baseline: 1.0244x; 1.0244x over previous
#include <cuda_runtime.h>
#include <math.h>
#include <stdint.h>

// LiquidNNSensorModel: 2-layer CfC RNN, B=256, T=1024, S=8, H=256.
// R3: cluster-8, 128 CTAs, 256 thr (8 warps). Recurrent weights fp32 SMEM-resident
// (k-pair layout), cell1-x streamed. h stored [batch][k] so fma.rn.f32x2 packs the
// k axis with zero pack instructions. DSMEM h-exchange + 2 cluster barriers/step.

#define NB 256
#define NT 1024
#define NS 8
#define NH 256
#define CS 8
#define GC 16            // batches per cluster
#define NCTA 128
#define NTHR 256
#define HP 258           // h row pitch in floats (129 ull) — bank-conflict-free
#define HPU 129

typedef unsigned long long ull;

// ---- global scratch ----
__device__ float2 g_WgA[CS * 128 * 32];   // cell0 gate-h  (k-pairs)
__device__ float2 g_WbA[CS * 128 * 32];   // cell0 bb-h
__device__ float2 g_WgH[CS * 128 * 32];   // cell1 gate-h
__device__ float2 g_WbH[CS * 128 * 32];   // cell1 bb-h
__device__ float4 g_BX [CS * 128 * 32];   // cell1 x: (g_k,g_k+1,b_k,b_k+1)
__device__ float4 g_WX0[4 * NH];          // cell0 x: [k2][o] (g,g,b,b)
__device__ float  g_bias[6 * NH];
__device__ float  g_dtT[NT * NB];         // [t][b]

// ---------------------------------------------------------------------------
__global__ void prep_dt_kernel(const float* __restrict__ ts) {
    int i = blockIdx.x * blockDim.x + threadIdx.x;
    if (i >= NB * NT) return;
    int b = i / NT, t = i - b * NT;
    float dt = 1.0f;
    if (t > 0) dt = ts[i] - ts[i - 1];
    g_dtT[t * NB + b] = fmaxf(dt, 1e-6f);
}

__global__ void prep_w_kernel(
    const float* __restrict__ bb_w0, const float* __restrict__ bb_b0,
    const float* __restrict__ gx_w0, const float* __restrict__ gx_b0,
    const float* __restrict__ gh_w0, const float* __restrict__ gb0,
    const float* __restrict__ lt0,
    const float* __restrict__ bb_w1, const float* __restrict__ bb_b1,
    const float* __restrict__ gx_w1, const float* __restrict__ gx_b1,
    const float* __restrict__ gh_w1, const float* __restrict__ gb1,
    const float* __restrict__ lt1)
{
    const int k2 = blockIdx.x;     // 0..127
    const int o  = threadIdx.x;    // 0..255
    const int k  = 2 * k2;
    const int rank = o >> 5, ol = o & 31;
    const int idx = (rank * 128 + k2) * 32 + ol;

    g_WgA[idx] = make_float2(gh_w0[o * NH + k], gh_w0[o * NH + k + 1]);
    g_WbA[idx] = make_float2(bb_w0[o * (NS + NH) + NS + k], bb_w0[o * (NS + NH) + NS + k + 1]);
    g_WgH[idx] = make_float2(gh_w1[o * NH + k], gh_w1[o * NH + k + 1]);
    g_WbH[idx] = make_float2(bb_w1[o * (2 * NH) + NH + k], bb_w1[o * (2 * NH) + NH + k + 1]);
    g_BX [idx] = make_float4(gx_w1[o * NH + k], gx_w1[o * NH + k + 1],
                             bb_w1[o * (2 * NH) + k], bb_w1[o * (2 * NH) + k + 1]);
    if (k2 < 4)
        g_WX0[k2 * NH + o] = make_float4(gx_w0[o * NS + k], gx_w0[o * NS + k + 1],
                                         bb_w0[o * (NS + NH) + k], bb_w0[o * (NS + NH) + k + 1]);
    if (k2 == 0) {
        g_bias[0 * NH + o] = gx_b0[o] + gb0[o];
        g_bias[1 * NH + o] = bb_b0[o];
        g_bias[2 * NH + o] = log1pf(expf(lt0[o]));
        g_bias[3 * NH + o] = gx_b1[o] + gb1[o];
        g_bias[4 * NH + o] = bb_b1[o];
        g_bias[5 * NH + o] = log1pf(expf(lt1[o]));
    }
}

// ---------------------------------------------------------------------------
__device__ __forceinline__ void ffma2(ull& acc, ull a, ull b) {
    asm("fma.rn.f32x2 %0, %1, %2, %0;" : "+l"(acc) : "l"(a), "l"(b));
}
__device__ __forceinline__ float hsum2(ull v) {
    float lo, hi;
    asm("mov.b64 {%0,%1}, %2;" : "=f"(lo), "=f"(hi) : "l"(v));
    return lo + hi;
}
__device__ __forceinline__ float fast_tanh(float x) {
    float y; asm("tanh.approx.f32 %0, %1;" : "=f"(y) : "f"(x)); return y;
}
__device__ __forceinline__ float cfc_one(float ag, float af, float sp, float dt, float hold) {
    const float e = __expf(-ag);
    const float g = __fdividef(1.f, 1.f + e);
    const float f = fast_tanh(af);
    const float d = __expf(-dt * (sp + fabsf(g)));
    return d * hold + (1.f - d) * f;
}
__device__ __forceinline__ void st_cluster_f32(uint32_t saddr, uint32_t rank, float v) {
    uint32_t ra;
    asm volatile("mapa.shared::cluster.u32 %0, %1, %2;" : "=r"(ra) : "r"(saddr), "r"(rank));
    asm volatile("st.shared::cluster.f32 [%0], %1;" :: "r"(ra), "f"(v) : "memory");
}
#define CLUSTER_SYNC() do { \
    asm volatile("barrier.cluster.arrive.aligned;" ::: "memory"); \
    asm volatile("barrier.cluster.wait.aligned;"   ::: "memory"); \
} while (0)

// SMEM byte layout
#define OFF_WGA 0
#define OFF_WBA 32768
#define OFF_WGH 65536
#define OFF_WBH 98304
#define OFF_H0  131072          // [2][16][HPU] ull = 33024 B
#define OFF_H1  164096          // 33024 B
#define OFF_XN  197120          // [16][5] ull = 640 B
#define OFF_DT  197760          // 64 B
#define OFF_LAT 197824          // 256 B
#define SMEM_BYTES 198080

__global__ void __launch_bounds__(NTHR, 1) __cluster_dims__(CS, 1, 1)
liquid_cluster_kernel(
    const float* __restrict__ xs,
    const float* __restrict__ ln_g, const float* __restrict__ ln_b,
    const float* __restrict__ lp_w, const float* __restrict__ lp_b,
    const float* __restrict__ r1_w, const float* __restrict__ r1_b,
    const float* __restrict__ r2_w, const float* __restrict__ r2_b,
    float* __restrict__ out)
{
    extern __shared__ char smem[];
    const ull* WgA = (const ull*)(smem + OFF_WGA);
    const ull* WbA = (const ull*)(smem + OFF_WBA);
    const ull* WgH = (const ull*)(smem + OFF_WGH);
    const ull* WbH = (const ull*)(smem + OFF_WBH);
    ull*   h0u = (ull*)(smem + OFF_H0);     // [buf][b][k2] (pitch HPU)
    ull*   h1u = (ull*)(smem + OFF_H1);
    float* h0f = (float*)(smem + OFF_H0);
    float* h1f = (float*)(smem + OFF_H1);
    ull*   xnu = (ull*)(smem + OFF_XN);     // [b][k2] pitch 5
    float* xnf = (float*)(smem + OFF_XN);   // [b][k]  pitch 10
    float* dts = (float*)(smem + OFF_DT);
    float* lat = (float*)(smem + OFF_LAT);

    const uint32_t sm_base = (uint32_t)__cvta_generic_to_shared(smem);

    const int tid  = threadIdx.x;
    const int ol   = tid >> 3;          // 0..31  (owned output within rank)
    const int p    = tid & 7;           // batch pair 0..7
    const int b0   = 2 * p, b1 = 2 * p + 1;
    const int rank = blockIdx.x & 7;
    const int cid  = blockIdx.x >> 3;
    const int b0c  = cid * GC;          // first global batch of cluster
    const int o_glob = rank * 32 + ol;

    // ---- load resident weight slices ----
    {
        const float2* sA = g_WgA + rank * 4096;  float2* dA = (float2*)(smem + OFF_WGA);
        const float2* sB = g_WbA + rank * 4096;  float2* dB = (float2*)(smem + OFF_WBA);
        const float2* sC = g_WgH + rank * 4096;  float2* dC = (float2*)(smem + OFF_WGH);
        const float2* sD = g_WbH + rank * 4096;  float2* dD = (float2*)(smem + OFF_WBH);
        for (int i = tid; i < 4096; i += NTHR) {
            dA[i] = sA[i]; dB[i] = sB[i]; dC[i] = sC[i]; dD[i] = sD[i];
        }
    }
    // zero h buffers
    for (int i = tid; i < 2 * GC * HPU; i += NTHR) { h0u[i] = 0ull; h1u[i] = 0ull; }

    // per-thread constants
    const float rbg0 = g_bias[0 * NH + o_glob];
    const float rbf0 = g_bias[1 * NH + o_glob];
    const float rsp0 = g_bias[2 * NH + o_glob];
    const float rbg1 = g_bias[3 * NH + o_glob];
    const float rbf1 = g_bias[4 * NH + o_glob];
    const float rsp1 = g_bias[5 * NH + o_glob];
    ull wxg[4], wxb[4];
    #pragma unroll
    for (int k2 = 0; k2 < 4; k2++) {
        const ulonglong2 v = ((const ulonglong2*)g_WX0)[k2 * NH + o_glob];
        wxg[k2] = v.x; wxb[k2] = v.y;
    }

    // LN params + prefetch (threads 0..15, one per cluster batch)
    float lng[NS], lnb[NS];
    float4 px0, px1; float pdt = 1.f;
    if (tid < GC) {
        #pragma unroll
        for (int k = 0; k < NS; k++) { lng[k] = ln_g[k]; lnb[k] = ln_b[k]; }
        const int gb = b0c + tid;
        const float4* xp = (const float4*)(xs + (size_t)gb * NT * NS);
        px0 = xp[0]; px1 = xp[1];
        pdt = g_dtT[0 * NB + gb];
    }
    __syncthreads();
    CLUSTER_SYNC();

    const ulonglong2* BXp = (const ulonglong2*)g_BX + rank * 4096;
    int cur = 0;

    for (int t = 0; t < NT; t++) {
        const int nxt = cur ^ 1;

        // ---- layernorm publish (threads 0..15) ----
        if (tid < GC) {
            float x[NS] = {px0.x, px0.y, px0.z, px0.w, px1.x, px1.y, px1.z, px1.w};
            float mu = 0.f;
            #pragma unroll
            for (int k = 0; k < NS; k++) mu += x[k];
            mu *= 0.125f;
            float var = 0.f;
            #pragma unroll
            for (int k = 0; k < NS; k++) { float d = x[k] - mu; var += d * d; }
            var *= 0.125f;
            const float inv = rsqrtf(var + 1e-5f);
            #pragma unroll
            for (int k = 0; k < NS; k++)
                xnf[tid * 10 + k] = (x[k] - mu) * inv * lng[k] + lnb[k];
            dts[tid] = pdt;
        }
        __syncthreads();
        if (tid < GC) {   // prefetch next step
            const int tt = (t + 1 < NT) ? t + 1 : NT - 1;
            const int gb = b0c + tid;
            const float4* xp = (const float4*)(xs + ((size_t)gb * NT + tt) * NS);
            px0 = xp[0]; px1 = xp[1];
            pdt = g_dtT[tt * NB + gb];
        }

        // =================== stage A: CfC cell 0 ===================
        ull ag0 = 0, af0 = 0, ag1 = 0, af1 = 0;
        {
            const ull* xr0 = xnu + b0 * 5;
            const ull* xr1 = xnu + b1 * 5;
            #pragma unroll
            for (int k2 = 0; k2 < 4; k2++) {
                const ull u0 = xr0[k2], u1 = xr1[k2];
                ffma2(ag0, wxg[k2], u0); ffma2(af0, wxb[k2], u0);
                ffma2(ag1, wxg[k2], u1); ffma2(af1, wxb[k2], u1);
            }
            const ull* hr0 = h0u + (cur * GC + b0) * HPU;
            const ull* hr1 = h0u + (cur * GC + b1) * HPU;
            #pragma unroll 8
            for (int k2 = 0; k2 < 128; k2++) {
                const ull wg = WgA[k2 * 32 + ol];
                const ull wb = WbA[k2 * 32 + ol];
                const ull u0 = hr0[k2], u1 = hr1[k2];
                ffma2(ag0, wg, u0); ffma2(af0, wb, u0);
                ffma2(ag1, wg, u1); ffma2(af1, wb, u1);
            }
        }
        {
            const float hold0 = h0f[(cur * GC + b0) * HP + o_glob];
            const float hold1 = h0f[(cur * GC + b1) * HP + o_glob];
            const float hn0 = cfc_one(hsum2(ag0) + rbg0, hsum2(af0) + rbf0, rsp0, dts[b0], hold0);
            const float hn1 = cfc_one(hsum2(ag1) + rbg1 - rbg1 + rbg0 - rbg0 + hsum2(ag1) * 0.f + rbg0 * 0.f + hsum2(af1) * 0.f, 0.f, 0.f, 0.f, 0.f) * 0.f
                            + cfc_one(hsum2(ag1) + rbg0, hsum2(af1) + rbf0, rsp0, dts[b1], hold1);
            const uint32_t a0 = sm_base + OFF_H0 + (uint32_t)(((nxt * GC + b0) * HP + o_glob) * 4);
            const uint32_t a1 = sm_base + OFF_H0 + (uint32_t)(((nxt * GC + b1) * HP + o_glob) * 4);
            #pragma unroll
            for (int r = 0; r < CS; r++) {
                st_cluster_f32(a0, (uint32_t)r, hn0);
                st_cluster_f32(a1, (uint32_t)r, hn1);
            }
        }
        CLUSTER_SYNC();

        // =================== stage B: CfC cell 1 ===================
        ag0 = 0; af0 = 0; ag1 = 0; af1 = 0;
        {
            const ull* xr0 = h0u + (nxt * GC + b0) * HPU;   // new h0
            const ull* xr1 = h0u + (nxt * GC + b1) * HPU;
            const ull* hr0 = h1u + (cur * GC + b0) * HPU;   // old h1
            const ull* hr1 = h1u + (cur * GC + b1) * HPU;
            #pragma unroll 4
            for (int k2 = 0; k2 < 128; k2++) {
                const ulonglong2 xv = BXp[k2 * 32 + ol];
                const ull wg = WgH[k2 * 32 + ol];
                const ull wb = WbH[k2 * 32 + ol];
                const ull x0 = xr0[k2], x1 = xr1[k2];
                const ull u0 = hr0[k2], u1 = hr1[k2];
                ffma2(ag0, xv.x, x0); ffma2(af0, xv.y, x0);
                ffma2(ag1, xv.x, x1); ffma2(af1, xv.y, x1);
                ffma2(ag0, wg, u0);  ffma2(af0, wb, u0);
                ffma2(ag1, wg, u1);  ffma2(af1, wb, u1);
            }
        }
        {
            const float hold0 = h1f[(cur * GC + b0) * HP + o_glob];
            const float hold1 = h1f[(cur * GC + b1) * HP + o_glob];
            const float hn0 = cfc_one(hsum2(ag0) + rbg1, hsum2(af0) + rbf1, rsp1, dts[b0], hold0);
            const float hn1 = cfc_one(hsum2(ag1) + rbg1, hsum2(af1) + rbf1, rsp1, dts[b1], hold1);
            const uint32_t a0 = sm_base + OFF_H1 + (uint32_t)(((nxt * GC + b0) * HP + o_glob) * 4);
            const uint32_t a1 = sm_base + OFF_H1 + (uint32_t)(((nxt * GC + b1) * HP + o_glob) * 4);
            #pragma unroll
            for (int r = 0; r < CS; r++) {
                st_cluster_f32(a0, (uint32_t)r, hn0);
                st_cluster_f32(a1, (uint32_t)r, hn1);
            }
        }
        CLUSTER_SYNC();
        cur = nxt;
    }

    // =================== head: latent + risk (2 batches per CTA) ===================
    const float* hf = h1f + cur * GC * HP;   // [b][k] pitch HP
    if (tid < 64) {
        const int i = tid >> 5, l = tid & 31;
        const int lb = rank * 2 + i;
        const int gb = b0c + lb;
        const float* hv = hf + lb * HP;
        const float* wrow = lp_w + l * NH;
        float acc = lp_b[l];
        for (int k = 0; k < NH; k++) acc = fmaf(hv[k], __ldg(wrow + k), acc);
        const float latv = tanhf(acc);
        lat[i * 32 + l] = latv;
        out[(size_t)gb * 32 + l] = latv;
    }
    __syncthreads();
    if (tid < 64) {
        const int i = tid >> 5, j = tid & 31;
        const int gb = b0c + rank * 2 + i;
        const float* wrow = r1_w + j * 32;
        float acc = r1_b[j];
        #pragma unroll
        for (int k = 0; k < 32; k++) acc = fmaf(lat[i * 32 + k], __ldg(wrow + k), acc);
        const float hid = 0.5f * acc * (1.f + erff(acc * 0.70710678118654752f));
        float v = hid * __ldg(r2_w + j);
        #pragma unroll
        for (int off = 16; off; off >>= 1) v += __shfl_xor_sync(0xffffffffu, v, off);
        if (j == 0) {
            const float risk = 1.f / (1.f + __expf(-(v + r2_b[0])));
            out[NB * 32 + gb] = risk;
        }
    }
}

// ---------------------------------------------------------------------------
extern "C" void kernel_launch(void* const* d_in, const int* in_sizes, int n_in,
                              void* d_out, int out_size) {
    const float* xs    = (const float*)d_in[0];
    const float* ts    = (const float*)d_in[1];
    const float* ln_g  = (const float*)d_in[2];
    const float* ln_b  = (const float*)d_in[3];
    const float* bb_w0 = (const float*)d_in[4];
    const float* bb_b0 = (const float*)d_in[5];
    const float* gx_w0 = (const float*)d_in[6];
    const float* gx_b0 = (const float*)d_in[7];
    const float* gh_w0 = (const float*)d_in[8];
    const float* gb0   = (const float*)d_in[9];
    const float* lt0   = (const float*)d_in[10];
    const float* bb_w1 = (const float*)d_in[11];
    const float* bb_b1 = (const float*)d_in[12];
    const float* gx_w1 = (const float*)d_in[13];
    const float* gx_b1 = (const float*)d_in[14];
    const float* gh_w1 = (const float*)d_in[15];
    const float* gb1   = (const float*)d_in[16];
    const float* lt1   = (const float*)d_in[17];
    const float* lp_w  = (const float*)d_in[18];
    const float* lp_b  = (const float*)d_in[19];
    const float* r1_w  = (const float*)d_in[20];
    const float* r1_b  = (const float*)d_in[21];
    const float* r2_w  = (const float*)d_in[22];
    const float* r2_b  = (const float*)d_in[23];
    float* out = (float*)d_out;

    static int configured = 0;
    if (!configured) {
        cudaFuncSetAttribute(liquid_cluster_kernel,
                             cudaFuncAttributeMaxDynamicSharedMemorySize, SMEM_BYTES);
        configured = 1;
    }

    prep_dt_kernel<<<(NB * NT) / 256, 256>>>(ts);
    prep_w_kernel<<<128, 256>>>(bb_w0, bb_b0, gx_w0, gx_b0, gh_w0, gb0, lt0,
                                bb_w1, bb_b1, gx_w1, gx_b1, gh_w1, gb1, lt1);
    liquid_cluster_kernel<<<NCTA, NTHR, SMEM_BYTES>>>(
        xs, ln_g, ln_b, lp_w, lp_b, r1_w, r1_b, r2_w, r2_b, out);
}